// round 11
// baseline (speedup 1.0000x reference)
#include <cuda_runtime.h>
#include <cuda_fp16.h>
#include <cstdint>

// IsokawaPytorchLayer as fp16 mma.sync GEMM (HMMA; tcgen05 is sm_103a-gated and
// the harness builds compute_103):
//   out[b, 4n+c] = sigmoid( sum_k X[b,k] * W[4n+c, k] )
// with X[b,0] := 1 and W[:,0] := -theta (x w-component == 0 makes col 0 free).
// R10: fix 8-way STS bank conflicts in A staging — each thread now assembles one
// full 16B fragment chunk (rows r and r+8) and writes a single conflict-free
// STS.128 (warp writes 512B contiguous). 4 STS.128/thread/tile vs 16 conflicted
// STS.32 before.

#define NDIM  256
#define MTILE 64
#define NTHR  512

#define SM_A0 0
#define SM_A1 32768
#define SM_B  65536
#define SM_TOTAL (65536 + 131072)

__device__ __align__(16) unsigned char g_Wfrag[131072];

// Left Hamilton matrix rows: c0 {w,-x,-y,-z} c1 {x,w,-z,y} c2 {y,z,w,-x} c3 {z,-y,x,w}
__device__ __forceinline__ float qcoef(float4 q, int c, int d) {
    float v = 0.0f;
    if (c == 0) v = (d == 0) ? q.x : (d == 1) ? -q.y : (d == 2) ? -q.z : -q.w;
    if (c == 1) v = (d == 0) ? q.y : (d == 1) ?  q.x : (d == 2) ? -q.w :  q.z;
    if (c == 2) v = (d == 0) ? q.z : (d == 1) ?  q.w : (d == 2) ?  q.x : -q.y;
    if (c == 3) v = (d == 0) ? q.w : (d == 1) ? -q.z : (d == 2) ?  q.y :  q.x;
    return v;
}

// Build W in fragment-ready layout: chunk t = [ks][ngroup][jb][lane], 16 bytes.
__global__ void build_w(const float4* __restrict__ wg,   // [64*64] (ww,wx,wy,wz)
                        const float4* __restrict__ tg)   // [64] theta
{
    int t = blockIdx.x * blockDim.x + threadIdx.x;       // 0..8191 chunk id
    int lane = t & 31, jb = (t >> 5) & 3, ngp = (t >> 7) & 3, ks = t >> 9;

    __half h[8];
    #pragma unroll
    for (int s = 0; s < 2; s++) {
        int f  = 2 * jb + s;
        int rr = ngp * 64 + f * 8 + (lane >> 2);         // W row index (4n+c)
        int n = rr >> 2, c = rr & 3;
        int k0 = ks * 16 + 2 * (lane & 3);
        int kk[4] = {k0, k0 + 1, k0 + 8, k0 + 9};
        #pragma unroll
        for (int i = 0; i < 4; i++) {
            int k = kk[i], m = k >> 2, d = k & 3;
            float4 q = wg[n * 64 + m];
            float v = qcoef(q, c, d);
            if (k == 0) {
                float4 th = tg[n];
                v = -((c == 0) ? th.x : (c == 1) ? th.y : (c == 2) ? th.z : th.w);
            }
            h[s * 4 + i] = __float2half_rn(v);
        }
    }
    *(uint4*)(g_Wfrag + t * 16) = *(const uint4*)h;
}

__device__ __forceinline__ float sigm(float s) {
    return __fdividef(1.0f, 1.0f + __expf(-s));
}

// Load one tile's worth of A data for this thread: thread (ks = tid>>5, L = tid&31)
// owns fragment chunk lane L of k-step ks for all 4 (mg,j) blocks.
// pf[blk*4 + {0,1,2,3}] = X{(r,kA),(r+8,kA),(r,kA+8),(r+8,kA+8)} as float2.
__device__ __forceinline__ void load_a(float2* pf, const float* xt, int ks, int L) {
    const int kA = ks * 16 + 2 * (L & 3);
    #pragma unroll
    for (int blk = 0; blk < 4; blk++) {
        int r = (blk >> 1) * 32 + (blk & 1) * 16 + (L >> 2);
        const float* p = xt + r * 256 + kA;
        pf[blk * 4 + 0] = *(const float2*)(p);
        pf[blk * 4 + 1] = *(const float2*)(p + 8 * 256);
        pf[blk * 4 + 2] = *(const float2*)(p + 8);
        pf[blk * 4 + 3] = *(const float2*)(p + 8 * 256 + 8);
    }
}

// Convert + store: one STS.128 per blk, conflict-free (warp = fixed ks writes
// 512B contiguous per blk).
__device__ __forceinline__ void stage_a(unsigned char* Abuf, const float2* pf, int ks, int L) {
    const bool bias = (ks == 0) && ((L & 3) == 0);   // kA == 0 chunk holds k=0
    #pragma unroll
    for (int blk = 0; blk < 4; blk++) {
        float2 rlo  = pf[blk * 4 + 0];
        float2 r8lo = pf[blk * 4 + 1];
        float2 rhi  = pf[blk * 4 + 2];
        float2 r8hi = pf[blk * 4 + 3];
        if (bias) { rlo.x = 1.0f; r8lo.x = 1.0f; }   // X[b,0] := 1 (xw==0 guaranteed)
        __half2 h[4];
        h[0] = __floats2half2_rn(rlo.x,  rlo.y);     // (r,   kA..kA+1)
        h[1] = __floats2half2_rn(r8lo.x, r8lo.y);    // (r+8, kA..kA+1)
        h[2] = __floats2half2_rn(rhi.x,  rhi.y);     // (r,   kA+8..kA+9)
        h[3] = __floats2half2_rn(r8hi.x, r8hi.y);    // (r+8, kA+8..kA+9)
        *(uint4*)(Abuf + ks * 2048 + blk * 512 + L * 16) = *(const uint4*)h;
    }
}

// Persistent GEMM: 16 warps = 2 mg (32 rows) x 8 ng (32 cols).
extern "C" __global__ void __launch_bounds__(NTHR, 1)
gemm_kernel(const float* __restrict__ xg, float* __restrict__ out, int ntiles)
{
    extern __shared__ unsigned char smem[];
    const int tid = threadIdx.x;

    // ---- load B once (fragment-ready) ----
    {
        const uint4* wb = (const uint4*)g_Wfrag;
        uint4* sb = (uint4*)(smem + SM_B);
        #pragma unroll
        for (int i = 0; i < 16; i++) sb[tid + i * NTHR] = wb[tid + i * NTHR];
    }

    const int sks = tid >> 5, sL = tid & 31;   // staging role
    int t = blockIdx.x;

    // ---- prologue: stage first tile into buf0 ----
    float2 pf[16];
    load_a(pf, xg + (size_t)t * (MTILE * 256), sks, sL);
    stage_a(smem + SM_A0, pf, sks, sL);
    __syncthreads();

    const int w = tid >> 5, lane = tid & 31;
    const int mg = w >> 3, ng = w & 7;
    const int colbase = ng * 32 + 2 * (lane & 3);
    const unsigned char* Bb = smem + SM_B + (ng >> 1) * 2048 + (ng & 1) * 1024 + lane * 16;

    int buf = 0;
    while (t < ntiles) {
        const int tn = t + (int)gridDim.x;
        const bool more = (tn < ntiles);

        // prefetch next tile (consumed after the MMA loop)
        if (more) load_a(pf, xg + (size_t)tn * (MTILE * 256), sks, sL);

        // ---- MMA over current buffer ----
        float acc[2][4][4];
        #pragma unroll
        for (int j = 0; j < 2; j++)
            #pragma unroll
            for (int f = 0; f < 4; f++)
                #pragma unroll
                for (int i = 0; i < 4; i++) acc[j][f][i] = 0.0f;

        const unsigned char* A = smem + (buf ? SM_A1 : SM_A0) + (mg * 2) * 512 + lane * 16;
        #pragma unroll
        for (int ks = 0; ks < 16; ks++) {
            uint4 a0 = *(const uint4*)(A + ks * 2048);
            uint4 a1 = *(const uint4*)(A + ks * 2048 + 512);
            uint4 b0 = *(const uint4*)(Bb + ks * 8192);
            uint4 b1 = *(const uint4*)(Bb + ks * 8192 + 512);
            #pragma unroll
            for (int j = 0; j < 2; j++) {
                const uint4& a = j ? a1 : a0;
                #pragma unroll
                for (int f = 0; f < 4; f++) {
                    const uint4& bq = (f >> 1) ? b1 : b0;
                    uint32_t r0 = (f & 1) ? bq.z : bq.x;
                    uint32_t r1 = (f & 1) ? bq.w : bq.y;
                    asm volatile(
                        "mma.sync.aligned.m16n8k16.row.col.f32.f16.f16.f32 "
                        "{%0,%1,%2,%3}, {%4,%5,%6,%7}, {%8,%9}, {%0,%1,%2,%3};"
                        : "+f"(acc[j][f][0]), "+f"(acc[j][f][1]),
                          "+f"(acc[j][f][2]), "+f"(acc[j][f][3])
                        : "r"(a.x), "r"(a.y), "r"(a.z), "r"(a.w),
                          "r"(r0), "r"(r1));
                }
            }
        }

        // ---- stage next tile into the other buffer ----
        if (more) stage_a(smem + (buf ? SM_A0 : SM_A1), pf, sks, sL);

        // ---- epilogue: sigmoid + store ----
        {
            const size_t rowbase = (size_t)t * MTILE + mg * 32 + (lane >> 2);
            #pragma unroll
            for (int j = 0; j < 2; j++) {
                size_t r0 = rowbase + j * 16;
                #pragma unroll
                for (int f = 0; f < 4; f++) {
                    int col = colbase + f * 8;
                    float2 o0, o1;
                    o0.x = sigm(acc[j][f][0]); o0.y = sigm(acc[j][f][1]);
                    o1.x = sigm(acc[j][f][2]); o1.y = sigm(acc[j][f][3]);
                    *(float2*)(out + r0 * NDIM + col)       = o0;
                    *(float2*)(out + (r0 + 8) * NDIM + col) = o1;
                }
            }
        }

        __syncthreads();   // staged tile visible; read buffer reusable next iter
        buf ^= 1;
        t = tn;
    }
}

extern "C" void kernel_launch(void* const* d_in, const int* in_sizes, int n_in,
                              void* d_out, int out_size) {
    const float*  xg = (const float*)d_in[0];    // (B, 64, 4) f32
    const float4* wg = (const float4*)d_in[1];   // (64, 64, 4) f32
    const float4* tg = (const float4*)d_in[2];   // (64, 4) f32
    float* out = (float*)d_out;

    int B = in_sizes[0] / 256;                   // 131072
    int ntiles = B / MTILE;                      // 2048
    int grid = 148;
    if (grid > ntiles) grid = ntiles;

    cudaFuncSetAttribute(gemm_kernel,
                         cudaFuncAttributeMaxDynamicSharedMemorySize, SM_TOTAL);

    build_w<<<32, 256>>>(wg, tg);
    gemm_kernel<<<grid, NTHR, SM_TOTAL>>>(xg, out, ntiles);
}

// round 12
// speedup vs baseline: 1.0636x; 1.0636x over previous
#include <cuda_runtime.h>
#include <cuda_fp16.h>
#include <cstdint>

// IsokawaPytorchLayer as fp16 mma.sync GEMM (HMMA; tcgen05 is sm_103a-gated and
// the harness builds compute_103):
//   out[b, 4n+c] = sigmoid( sum_k X[b,k] * W[4n+c, k] )
// with X[b,0] := 1 and W[:,0] := -theta (x w-component == 0 makes col 0 free).
// R11: L1-wavefront diet. Coalesced LDG staging (512B/warp contiguous, 4 wf/instr)
// AND low-conflict STS by XOR-swizzling the fragment chunk index with ks
// (store chunk c at c^ks; MMA reads lane^ks — still one conflict-free LDS.128).

#define NDIM  256
#define MTILE 64
#define NTHR  512

#define SM_A0 0
#define SM_A1 32768
#define SM_B  65536
#define SM_TOTAL (65536 + 131072)

__device__ __align__(16) unsigned char g_Wfrag[131072];

// Left Hamilton matrix rows: c0 {w,-x,-y,-z} c1 {x,w,-z,y} c2 {y,z,w,-x} c3 {z,-y,x,w}
__device__ __forceinline__ float qcoef(float4 q, int c, int d) {
    float v = 0.0f;
    if (c == 0) v = (d == 0) ? q.x : (d == 1) ? -q.y : (d == 2) ? -q.z : -q.w;
    if (c == 1) v = (d == 0) ? q.y : (d == 1) ?  q.x : (d == 2) ? -q.w :  q.z;
    if (c == 2) v = (d == 0) ? q.z : (d == 1) ?  q.w : (d == 2) ?  q.x : -q.y;
    if (c == 3) v = (d == 0) ? q.w : (d == 1) ? -q.z : (d == 2) ?  q.y :  q.x;
    return v;
}

// Build W in fragment-ready layout: chunk t = [ks][ngroup][jb][lane], 16 bytes.
// (B is NOT ks-XOR-swizzled; only A staging is.)
__global__ void build_w(const float4* __restrict__ wg,   // [64*64] (ww,wx,wy,wz)
                        const float4* __restrict__ tg)   // [64] theta
{
    int t = blockIdx.x * blockDim.x + threadIdx.x;       // 0..8191 chunk id
    int lane = t & 31, jb = (t >> 5) & 3, ngp = (t >> 7) & 3, ks = t >> 9;

    __half h[8];
    #pragma unroll
    for (int s = 0; s < 2; s++) {
        int f  = 2 * jb + s;
        int rr = ngp * 64 + f * 8 + (lane >> 2);         // W row index (4n+c)
        int n = rr >> 2, c = rr & 3;
        int k0 = ks * 16 + 2 * (lane & 3);
        int kk[4] = {k0, k0 + 1, k0 + 8, k0 + 9};
        #pragma unroll
        for (int i = 0; i < 4; i++) {
            int k = kk[i], m = k >> 2, d = k & 3;
            float4 q = wg[n * 64 + m];
            float v = qcoef(q, c, d);
            if (k == 0) {
                float4 th = tg[n];
                v = -((c == 0) ? th.x : (c == 1) ? th.y : (c == 2) ? th.z : th.w);
            }
            h[s * 4 + i] = __float2half_rn(v);
        }
    }
    *(uint4*)(g_Wfrag + t * 16) = *(const uint4*)h;
}

__device__ __forceinline__ float sigm(float s) {
    return __fdividef(1.0f, 1.0f + __expf(-s));
}

// Stage one prefetched A tile into XOR-swizzled fragment layout.
// Thread role: kq = tid&63 (uint4 col), rb = tid>>6. pf[it] = X row (it*8+rb),
// f32 cols 4kq..4kq+3 (coalesced LDG). Each uint4 -> two half2 pieces going to
// chunks (lane_d)^ks and (lane_d+1)^ks of block (ks, mg*2+j).
__device__ __forceinline__ void stage_a(unsigned char* Abuf, const uint4* pf,
                                        int kq, int rb) {
    const int ks     = kq >> 2;
    const int lane_d = 4 * rb + 2 * (kq & 1);
    const int sub    = ((kq >> 1) & 1) * 8;
    const int c0     = (lane_d)     ^ ks;
    const int c1     = (lane_d + 1) ^ ks;
    #pragma unroll
    for (int it = 0; it < 8; it++) {
        float4 v = *(const float4*)&pf[it];
        if (kq == 0) v.x = 1.0f;             // X[b,0] := 1 (xw==0 guaranteed)
        int base  = ks * 2048 + ((it >> 2) * 2 + ((it >> 1) & 1)) * 512;
        int piece = (it & 1) * 4 + sub;
        *(__half2*)(Abuf + base + c0 * 16 + piece) = __floats2half2_rn(v.x, v.y);
        *(__half2*)(Abuf + base + c1 * 16 + piece) = __floats2half2_rn(v.z, v.w);
    }
}

// Persistent GEMM: 16 warps = 2 mg (32 rows) x 8 ng (32 cols).
extern "C" __global__ void __launch_bounds__(NTHR, 1)
gemm_kernel(const uint4* __restrict__ xg, float* __restrict__ out, int ntiles)
{
    extern __shared__ unsigned char smem[];
    const int tid = threadIdx.x;

    // ---- load B once (fragment-ready) ----
    {
        const uint4* wb = (const uint4*)g_Wfrag;
        uint4* sb = (uint4*)(smem + SM_B);
        #pragma unroll
        for (int i = 0; i < 16; i++) sb[tid + i * NTHR] = wb[tid + i * NTHR];
    }

    const int kq = tid & 63, rb = tid >> 6;    // staging role
    int t = blockIdx.x;

    // ---- prologue: stage first tile into buf0 (coalesced LDG.128) ----
    uint4 pf[8];
    #pragma unroll
    for (int it = 0; it < 8; it++) pf[it] = xg[(size_t)t * 4096 + it * 512 + tid];
    stage_a(smem + SM_A0, pf, kq, rb);
    __syncthreads();

    const int w = tid >> 5, lane = tid & 31;
    const int mg = w >> 3, ng = w & 7;
    const int colbase = ng * 32 + 2 * (lane & 3);
    const unsigned char* Bb = smem + SM_B + (ng >> 1) * 2048 + (ng & 1) * 1024 + lane * 16;

    int buf = 0;
    while (t < ntiles) {
        const int tn = t + (int)gridDim.x;
        const bool more = (tn < ntiles);

        // prefetch next tile (coalesced; consumed after the MMA loop)
        if (more) {
            #pragma unroll
            for (int it = 0; it < 8; it++)
                pf[it] = xg[(size_t)tn * 4096 + it * 512 + tid];
        }

        // ---- MMA over current buffer ----
        float acc[2][4][4];
        #pragma unroll
        for (int j = 0; j < 2; j++)
            #pragma unroll
            for (int f = 0; f < 4; f++)
                #pragma unroll
                for (int i = 0; i < 4; i++) acc[j][f][i] = 0.0f;

        const unsigned char* A = smem + (buf ? SM_A1 : SM_A0) + (mg * 2) * 512;
        #pragma unroll
        for (int ks = 0; ks < 16; ks++) {
            const int lx = (lane ^ ks) * 16;           // ks-XOR chunk placement
            uint4 a0 = *(const uint4*)(A + ks * 2048 + lx);
            uint4 a1 = *(const uint4*)(A + ks * 2048 + 512 + lx);
            uint4 b0 = *(const uint4*)(Bb + ks * 8192);
            uint4 b1 = *(const uint4*)(Bb + ks * 8192 + 512);
            #pragma unroll
            for (int j = 0; j < 2; j++) {
                const uint4& a = j ? a1 : a0;
                #pragma unroll
                for (int f = 0; f < 4; f++) {
                    const uint4& bq = (f >> 1) ? b1 : b0;
                    uint32_t r0 = (f & 1) ? bq.z : bq.x;
                    uint32_t r1 = (f & 1) ? bq.w : bq.y;
                    asm volatile(
                        "mma.sync.aligned.m16n8k16.row.col.f32.f16.f16.f32 "
                        "{%0,%1,%2,%3}, {%4,%5,%6,%7}, {%8,%9}, {%0,%1,%2,%3};"
                        : "+f"(acc[j][f][0]), "+f"(acc[j][f][1]),
                          "+f"(acc[j][f][2]), "+f"(acc[j][f][3])
                        : "r"(a.x), "r"(a.y), "r"(a.z), "r"(a.w),
                          "r"(r0), "r"(r1));
                }
            }
        }

        // ---- stage next tile into the other buffer ----
        if (more) stage_a(smem + (buf ? SM_A0 : SM_A1), pf, kq, rb);

        // ---- epilogue: sigmoid + store ----
        {
            const size_t rowbase = (size_t)t * MTILE + mg * 32 + (lane >> 2);
            #pragma unroll
            for (int j = 0; j < 2; j++) {
                size_t r0 = rowbase + j * 16;
                #pragma unroll
                for (int f = 0; f < 4; f++) {
                    int col = colbase + f * 8;
                    float2 o0, o1;
                    o0.x = sigm(acc[j][f][0]); o0.y = sigm(acc[j][f][1]);
                    o1.x = sigm(acc[j][f][2]); o1.y = sigm(acc[j][f][3]);
                    *(float2*)(out + r0 * NDIM + col)       = o0;
                    *(float2*)(out + (r0 + 8) * NDIM + col) = o1;
                }
            }
        }

        __syncthreads();   // staged tile visible; read buffer reusable next iter
        buf ^= 1;
        t = tn;
    }
}

extern "C" void kernel_launch(void* const* d_in, const int* in_sizes, int n_in,
                              void* d_out, int out_size) {
    const uint4*  xg = (const uint4*)d_in[0];    // (B, 64, 4) f32
    const float4* wg = (const float4*)d_in[1];   // (64, 64, 4) f32
    const float4* tg = (const float4*)d_in[2];   // (64, 4) f32
    float* out = (float*)d_out;

    int B = in_sizes[0] / 256;                   // 131072
    int ntiles = B / MTILE;                      // 2048
    int grid = 148;
    if (grid > ntiles) grid = ntiles;

    cudaFuncSetAttribute(gemm_kernel,
                         cudaFuncAttributeMaxDynamicSharedMemorySize, SM_TOTAL);

    build_w<<<32, 256>>>(wg, tg);
    gemm_kernel<<<grid, NTHR, SM_TOTAL>>>(xg, out, ntiles);
}

// round 13
// speedup vs baseline: 1.1345x; 1.0666x over previous
#include <cuda_runtime.h>
#include <cuda_fp16.h>
#include <cstdint>

// IsokawaPytorchLayer as fp16 mma.sync GEMM (HMMA; tcgen05 is sm_103a-gated and
// the harness builds compute_103):
//   out[b, 4n+c] = sigmoid( sum_k X[b,k] * W[4n+c, k] )
// with X[b,0] := 1 and W[:,0] := -theta (x w-component == 0 makes col 0 free).
// R12: warp specialization (8 producer + 8 consumer warps) and 32x64 consumer
// warp tiles. Producers stage tile t+1 (LDG f32 -> cvt -> XOR-swizzled STS)
// while consumers run MMA + sigmoid epilogue on tile t. MMA-LDS wavefronts
// drop 4096 -> 3072 per tile; staging leaves the consumer critical path.

#define NDIM  256
#define MTILE 64
#define NTHR  512

#define SM_A0 0
#define SM_A1 32768
#define SM_B  65536
#define SM_TOTAL (65536 + 131072)

__device__ __align__(16) unsigned char g_Wfrag[131072];

// Left Hamilton matrix rows: c0 {w,-x,-y,-z} c1 {x,w,-z,y} c2 {y,z,w,-x} c3 {z,-y,x,w}
__device__ __forceinline__ float qcoef(float4 q, int c, int d) {
    float v = 0.0f;
    if (c == 0) v = (d == 0) ? q.x : (d == 1) ? -q.y : (d == 2) ? -q.z : -q.w;
    if (c == 1) v = (d == 0) ? q.y : (d == 1) ?  q.x : (d == 2) ? -q.w :  q.z;
    if (c == 2) v = (d == 0) ? q.z : (d == 1) ?  q.w : (d == 2) ?  q.x : -q.y;
    if (c == 3) v = (d == 0) ? q.w : (d == 1) ? -q.z : (d == 2) ?  q.y :  q.x;
    return v;
}

// Build W in fragment-ready layout: chunk t = [ks][ngroup][jb][lane], 16 bytes.
__global__ void build_w(const float4* __restrict__ wg,   // [64*64] (ww,wx,wy,wz)
                        const float4* __restrict__ tg)   // [64] theta
{
    int t = blockIdx.x * blockDim.x + threadIdx.x;       // 0..8191 chunk id
    int lane = t & 31, jb = (t >> 5) & 3, ngp = (t >> 7) & 3, ks = t >> 9;

    __half h[8];
    #pragma unroll
    for (int s = 0; s < 2; s++) {
        int f  = 2 * jb + s;
        int rr = ngp * 64 + f * 8 + (lane >> 2);         // W row index (4n+c)
        int n = rr >> 2, c = rr & 3;
        int k0 = ks * 16 + 2 * (lane & 3);
        int kk[4] = {k0, k0 + 1, k0 + 8, k0 + 9};
        #pragma unroll
        for (int i = 0; i < 4; i++) {
            int k = kk[i], m = k >> 2, d = k & 3;
            float4 q = wg[n * 64 + m];
            float v = qcoef(q, c, d);
            if (k == 0) {
                float4 th = tg[n];
                v = -((c == 0) ? th.x : (c == 1) ? th.y : (c == 2) ? th.z : th.w);
            }
            h[s * 4 + i] = __float2half_rn(v);
        }
    }
    *(uint4*)(g_Wfrag + t * 16) = *(const uint4*)h;
}

__device__ __forceinline__ float sigm(float s) {
    return __fdividef(1.0f, 1.0f + __expf(-s));
}

// Producer: load 8 rows-worth (it0..it0+7) for this thread's (rb4, kq) role.
// Row r = 4*it + rb4, f32 cols 4kq..4kq+3. Coalesced: warp spans kq 0..31.
__device__ __forceinline__ void load8(float4* pf, const float4* xt, int it0,
                                      int rb4, int kq) {
    #pragma unroll
    for (int i = 0; i < 8; i++) {
        int r = 4 * (it0 + i) + rb4;
        pf[i] = xt[r * 64 + kq];
    }
}

// Producer: cvt + STS into XOR-swizzled fragment layout.
// Chunk contract (consumer reads 16B chunk (lane^ks) of block r>>4):
//   x=(r,kA) y=(r+8,kA) z=(r,kA+8) w=(r+8,kA+8), kA = 16*ks + 2*(L&3).
__device__ __forceinline__ void stage8(unsigned char* Abuf, const float4* pf,
                                       int it0, int rb4, int kq) {
    const int ks  = kq >> 2;
    const int sub = ((kq >> 1) & 1) * 8;
    const int t4  = 2 * (kq & 1);
    #pragma unroll
    for (int i = 0; i < 8; i++) {
        int r = 4 * (it0 + i) + rb4;
        float4 v = pf[i];
        if (kq == 0) v.x = 1.0f;                 // X[b,0] := 1 (xw==0 guaranteed)
        int lane_lo = 4 * (r & 7) + t4;
        int c0 = lane_lo ^ ks;
        int c1 = (lane_lo + 1) ^ ks;
        int base = ks * 2048 + ((r >> 4) & 3) * 512 + ((r >> 3) & 1) * 4 + sub;
        *(__half2*)(Abuf + base + c0 * 16) = __floats2half2_rn(v.x, v.y);
        *(__half2*)(Abuf + base + c1 * 16) = __floats2half2_rn(v.z, v.w);
    }
}

// Persistent GEMM. Warps 0..7: consumers (2 mg x 4 ng, warp tile 32x64).
// Warps 8..15: producers (stage tile t+grid while consumers work on t).
extern "C" __global__ void __launch_bounds__(NTHR, 1)
gemm_kernel(const float4* __restrict__ xg, float* __restrict__ out, int ntiles)
{
    extern __shared__ unsigned char smem[];
    const int tid = threadIdx.x;

    // ---- load B once (fragment-ready, all 512 threads) ----
    {
        const uint4* wb = (const uint4*)g_Wfrag;
        uint4* sb = (uint4*)(smem + SM_B);
        #pragma unroll
        for (int i = 0; i < 16; i++) sb[tid + i * NTHR] = wb[tid + i * NTHR];
    }

    const bool is_prod = (tid >= 256);
    int t = blockIdx.x;

    if (is_prod) {
        // ---------------- PRODUCER ----------------
        const int ptid = tid - 256;
        const int kq = ptid & 63, rb4 = ptid >> 6;
        float4 pf[8];

        // prologue: stage tile t into buf0
        {
            const float4* xt = xg + (size_t)t * 4096;
            load8(pf, xt, 0, rb4, kq);
            stage8(smem + SM_A0, pf, 0, rb4, kq);
            load8(pf, xt, 8, rb4, kq);
            stage8(smem + SM_A0, pf, 8, rb4, kq);
        }
        __syncthreads();

        int buf = 0;
        while (t < ntiles) {
            const int tn = t + (int)gridDim.x;
            if (tn < ntiles) {
                unsigned char* Ab = smem + (buf ? SM_A0 : SM_A1);
                const float4* xt = xg + (size_t)tn * 4096;
                load8(pf, xt, 0, rb4, kq);
                stage8(Ab, pf, 0, rb4, kq);
                load8(pf, xt, 8, rb4, kq);
                stage8(Ab, pf, 8, rb4, kq);
            }
            __syncthreads();
            buf ^= 1;
            t = tn;
        }
    } else {
        // ---------------- CONSUMER ----------------
        const int w = tid >> 5, lane = tid & 31;
        const int mg = w >> 2, ng = w & 3;             // warp tile 32 x 64
        const int colbase = ng * 64 + 2 * (lane & 3);
        const unsigned char* Bb = smem + SM_B + ng * 2048 + lane * 16;

        __syncthreads();                               // buf0 ready

        int buf = 0;
        while (t < ntiles) {
            float acc[2][8][4];
            #pragma unroll
            for (int j = 0; j < 2; j++)
                #pragma unroll
                for (int f = 0; f < 8; f++)
                    #pragma unroll
                    for (int i = 0; i < 4; i++) acc[j][f][i] = 0.0f;

            const unsigned char* A = smem + (buf ? SM_A1 : SM_A0) + (mg * 2) * 512;
            #pragma unroll
            for (int ks = 0; ks < 16; ks++) {
                const int lx = (lane ^ ks) * 16;       // ks-XOR chunk placement
                uint4 a0 = *(const uint4*)(A + ks * 2048 + lx);
                uint4 a1 = *(const uint4*)(A + ks * 2048 + 512 + lx);
                uint4 bq[4];
                #pragma unroll
                for (int jb = 0; jb < 4; jb++)
                    bq[jb] = *(const uint4*)(Bb + ks * 8192 + jb * 512);
                #pragma unroll
                for (int j = 0; j < 2; j++) {
                    const uint4& a = j ? a1 : a0;
                    #pragma unroll
                    for (int f = 0; f < 8; f++) {
                        const uint4& b = bq[f >> 1];
                        uint32_t r0 = (f & 1) ? b.z : b.x;
                        uint32_t r1 = (f & 1) ? b.w : b.y;
                        asm volatile(
                            "mma.sync.aligned.m16n8k16.row.col.f32.f16.f16.f32 "
                            "{%0,%1,%2,%3}, {%4,%5,%6,%7}, {%8,%9}, {%0,%1,%2,%3};"
                            : "+f"(acc[j][f][0]), "+f"(acc[j][f][1]),
                              "+f"(acc[j][f][2]), "+f"(acc[j][f][3])
                            : "r"(a.x), "r"(a.y), "r"(a.z), "r"(a.w),
                              "r"(r0), "r"(r1));
                    }
                }
            }

            // epilogue: sigmoid + store
            {
                const size_t rowbase = (size_t)t * MTILE + mg * 32 + (lane >> 2);
                #pragma unroll
                for (int j = 0; j < 2; j++) {
                    size_t r0 = rowbase + j * 16;
                    #pragma unroll
                    for (int f = 0; f < 8; f++) {
                        int col = colbase + f * 8;
                        float2 o0, o1;
                        o0.x = sigm(acc[j][f][0]); o0.y = sigm(acc[j][f][1]);
                        o1.x = sigm(acc[j][f][2]); o1.y = sigm(acc[j][f][3]);
                        *(float2*)(out + r0 * NDIM + col)       = o0;
                        *(float2*)(out + (r0 + 8) * NDIM + col) = o1;
                    }
                }
            }

            __syncthreads();    // next buffer staged; current reusable
            buf ^= 1;
            t += (int)gridDim.x;
        }
    }
}

extern "C" void kernel_launch(void* const* d_in, const int* in_sizes, int n_in,
                              void* d_out, int out_size) {
    const float4* xg = (const float4*)d_in[0];   // (B, 64, 4) f32
    const float4* wg = (const float4*)d_in[1];   // (64, 64, 4) f32
    const float4* tg = (const float4*)d_in[2];   // (64, 4) f32
    float* out = (float*)d_out;

    int B = in_sizes[0] / 256;                   // 131072
    int ntiles = B / MTILE;                      // 2048
    int grid = 148;
    if (grid > ntiles) grid = ntiles;

    cudaFuncSetAttribute(gemm_kernel,
                         cudaFuncAttributeMaxDynamicSharedMemorySize, SM_TOTAL);

    build_w<<<32, 256>>>(wg, tg);
    gemm_kernel<<<grid, NTHR, SM_TOTAL>>>(xg, out, ntiles);
}

// round 14
// speedup vs baseline: 1.2002x; 1.0579x over previous
#include <cuda_runtime.h>
#include <cuda_fp16.h>
#include <cstdint>

// IsokawaPytorchLayer as fp16 mma.sync GEMM (HMMA; tcgen05 is sm_103a-gated and
// the harness builds compute_103):
//   out[b, 4n+c] = sigmoid( sum_k X[b,k] * W[4n+c, k] )
// with X[b,0] := 1 and W[:,0] := -theta (x w-component == 0 makes col 0 free).
// R13: (1) 64x64 consumer warp tiles (4 consumers + 4 producers, 256 thr) ->
// B-LDS halves; (2) W column permutation so the epilogue emits STG.128 of 4
// consecutive floats per lane (STG wf halves, no shuffles); (3) tanh.approx
// sigmoid (1 MUFU instead of EX2+RCP).

#define NDIM  256
#define MTILE 64
#define NTHR  256

#define SM_A0 0
#define SM_A1 32768
#define SM_B  65536
#define SM_TOTAL (65536 + 131072)

__device__ __align__(16) unsigned char g_Wfrag[131072];

// Left Hamilton matrix rows: c0 {w,-x,-y,-z} c1 {x,w,-z,y} c2 {y,z,w,-x} c3 {z,-y,x,w}
__device__ __forceinline__ float qcoef(float4 q, int c, int d) {
    float v = 0.0f;
    if (c == 0) v = (d == 0) ? q.x : (d == 1) ? -q.y : (d == 2) ? -q.z : -q.w;
    if (c == 1) v = (d == 0) ? q.y : (d == 1) ?  q.x : (d == 2) ? -q.w :  q.z;
    if (c == 2) v = (d == 0) ? q.z : (d == 1) ?  q.w : (d == 2) ?  q.x : -q.y;
    if (c == 3) v = (d == 0) ? q.w : (d == 1) ? -q.z : (d == 2) ?  q.y :  q.x;
    return v;
}

// Build W in fragment-ready layout: chunk t = [ks][ngroup][jb][lane], 16 bytes.
// COLUMN PERMUTATION: fragment (f = 2*jb+s), n-within-frag v = lane>>2 maps to
// physical row  ngp*64 + 16*jb + 4*(v>>1) + 2*s + (v&1)
// so that in the epilogue, lane q's {f=2i:[c0,c1], f=2i+1:[c0,c1]} are the 4
// consecutive outputs at col 16*i + 4*q  ->  single STG.128 per (row, pair).
__global__ void build_w(const float4* __restrict__ wg,   // [64*64] (ww,wx,wy,wz)
                        const float4* __restrict__ tg)   // [64] theta
{
    int t = blockIdx.x * blockDim.x + threadIdx.x;       // 0..8191 chunk id
    int lane = t & 31, jb = (t >> 5) & 3, ngp = (t >> 7) & 3, ks = t >> 9;

    __half h[8];
    #pragma unroll
    for (int s = 0; s < 2; s++) {
        int v  = lane >> 2;                              // n-index within fragment
        int rr = ngp * 64 + 16 * jb + 4 * (v >> 1) + 2 * s + (v & 1);  // permuted W row
        int n = rr >> 2, c = rr & 3;
        int k0 = ks * 16 + 2 * (lane & 3);
        int kk[4] = {k0, k0 + 1, k0 + 8, k0 + 9};
        #pragma unroll
        for (int i = 0; i < 4; i++) {
            int k = kk[i], m = k >> 2, d = k & 3;
            float4 q = wg[n * 64 + m];
            float vv = qcoef(q, c, d);
            if (k == 0) {
                float4 th = tg[n];
                vv = -((c == 0) ? th.x : (c == 1) ? th.y : (c == 2) ? th.z : th.w);
            }
            h[s * 4 + i] = __float2half_rn(vv);
        }
    }
    *(uint4*)(g_Wfrag + t * 16) = *(const uint4*)h;
}

// sigmoid(s) = 0.5 + 0.5*tanh(s/2): one MUFU.TANH + FFMA (vs EX2+RCP before).
__device__ __forceinline__ float sigm(float s) {
    float r;
    asm("tanh.approx.f32 %0, %1;" : "=f"(r) : "f"(s * 0.5f));
    return fmaf(0.5f, r, 0.5f);
}

// Producer staging: thread role (kq = f32-quad col 0..63, rb2 = row parity).
// Chunk contract (consumer reads 16B chunk (lane^ks) of block (r>>4)&3):
//   x=(r,kA) y=(r+8,kA) z=(r,kA+8) w=(r+8,kA+8), kA = 16*ks + 2*(L&3).
__device__ __forceinline__ void stage_tile(unsigned char* Ab, const float4* xt,
                                           int kq, int rb2) {
    const int ks  = kq >> 2;
    const int sub = ((kq >> 1) & 1) * 8;
    const int t4  = 2 * (kq & 1);
    float4 pf[8];
    #pragma unroll
    for (int bch = 0; bch < 4; bch++) {
        #pragma unroll
        for (int i = 0; i < 8; i++) {
            int r = 2 * (bch * 8 + i) + rb2;
            pf[i] = xt[r * 64 + kq];
        }
        #pragma unroll
        for (int i = 0; i < 8; i++) {
            int r = 2 * (bch * 8 + i) + rb2;
            float4 v = pf[i];
            if (kq == 0) v.x = 1.0f;             // X[b,0] := 1 (xw==0 guaranteed)
            int lane_lo = 4 * (r & 7) + t4;
            int c0 = lane_lo ^ ks;
            int c1 = (lane_lo + 1) ^ ks;
            int base = ks * 2048 + ((r >> 4) & 3) * 512 + ((r >> 3) & 1) * 4 + sub;
            *(__half2*)(Ab + base + c0 * 16) = __floats2half2_rn(v.x, v.y);
            *(__half2*)(Ab + base + c1 * 16) = __floats2half2_rn(v.z, v.w);
        }
    }
}

// Persistent GEMM. Warps 0..3: consumers, warp tile 64x64 (ng = warp id).
// Warps 4..7: producers (stage tile t+grid while consumers work on t).
extern "C" __global__ void __launch_bounds__(NTHR, 1)
gemm_kernel(const float4* __restrict__ xg, float* __restrict__ out, int ntiles)
{
    extern __shared__ unsigned char smem[];
    const int tid = threadIdx.x;

    // ---- load B once (fragment-ready, all 256 threads) ----
    {
        const uint4* wb = (const uint4*)g_Wfrag;
        uint4* sb = (uint4*)(smem + SM_B);
        #pragma unroll
        for (int i = 0; i < 32; i++) sb[tid + i * NTHR] = wb[tid + i * NTHR];
    }

    const bool is_prod = (tid >= 128);
    int t = blockIdx.x;

    if (is_prod) {
        // ---------------- PRODUCER ----------------
        const int ptid = tid - 128;
        const int kq = ptid & 63, rb2 = ptid >> 6;

        stage_tile(smem + SM_A0, xg + (size_t)t * 4096, kq, rb2);
        __syncthreads();

        int buf = 0;
        while (t < ntiles) {
            const int tn = t + (int)gridDim.x;
            if (tn < ntiles)
                stage_tile(smem + (buf ? SM_A0 : SM_A1),
                           xg + (size_t)tn * 4096, kq, rb2);
            __syncthreads();
            buf ^= 1;
            t = tn;
        }
    } else {
        // ---------------- CONSUMER ----------------
        const int w = tid >> 5, lane = tid & 31;
        const int ng = w;                               // warp tile 64 x 64
        const unsigned char* Bb = smem + SM_B + ng * 2048 + lane * 16;

        __syncthreads();                                // buf0 ready

        int buf = 0;
        while (t < ntiles) {
            float acc[4][8][4];
            #pragma unroll
            for (int j = 0; j < 4; j++)
                #pragma unroll
                for (int f = 0; f < 8; f++)
                    #pragma unroll
                    for (int i = 0; i < 4; i++) acc[j][f][i] = 0.0f;

            const unsigned char* A = smem + (buf ? SM_A1 : SM_A0);
            #pragma unroll
            for (int ks = 0; ks < 16; ks++) {
                const int lx = (lane ^ ks) * 16;        // ks-XOR chunk placement
                uint4 a[4];
                #pragma unroll
                for (int j = 0; j < 4; j++)
                    a[j] = *(const uint4*)(A + ks * 2048 + j * 512 + lx);
                uint4 bq[4];
                #pragma unroll
                for (int jb = 0; jb < 4; jb++)
                    bq[jb] = *(const uint4*)(Bb + ks * 8192 + jb * 512);
                #pragma unroll
                for (int j = 0; j < 4; j++) {
                    #pragma unroll
                    for (int f = 0; f < 8; f++) {
                        const uint4& b = bq[f >> 1];
                        uint32_t r0 = (f & 1) ? b.z : b.x;
                        uint32_t r1 = (f & 1) ? b.w : b.y;
                        asm volatile(
                            "mma.sync.aligned.m16n8k16.row.col.f32.f16.f16.f32 "
                            "{%0,%1,%2,%3}, {%4,%5,%6,%7}, {%8,%9}, {%0,%1,%2,%3};"
                            : "+f"(acc[j][f][0]), "+f"(acc[j][f][1]),
                              "+f"(acc[j][f][2]), "+f"(acc[j][f][3])
                            : "r"(a[j].x), "r"(a[j].y), "r"(a[j].z), "r"(a[j].w),
                              "r"(r0), "r"(r1));
                    }
                }
            }

            // epilogue: sigmoid + permuted STG.128 (4 consecutive floats/lane)
            {
                const int q = lane & 3;
                const size_t rowbase = (size_t)t * MTILE + (lane >> 2);
                #pragma unroll
                for (int j = 0; j < 4; j++) {
                    size_t r0 = rowbase + j * 16;
                    #pragma unroll
                    for (int i = 0; i < 4; i++) {
                        int col = ng * 64 + 16 * i + 4 * q;
                        float4 v0, v1;
                        v0.x = sigm(acc[j][2 * i][0]);     v0.y = sigm(acc[j][2 * i][1]);
                        v0.z = sigm(acc[j][2 * i + 1][0]); v0.w = sigm(acc[j][2 * i + 1][1]);
                        v1.x = sigm(acc[j][2 * i][2]);     v1.y = sigm(acc[j][2 * i][3]);
                        v1.z = sigm(acc[j][2 * i + 1][2]); v1.w = sigm(acc[j][2 * i + 1][3]);
                        *(float4*)(out + r0 * NDIM + col)       = v0;
                        *(float4*)(out + (r0 + 8) * NDIM + col) = v1;
                    }
                }
            }

            __syncthreads();    // next buffer staged; current reusable
            buf ^= 1;
            t += (int)gridDim.x;
        }
    }
}

extern "C" void kernel_launch(void* const* d_in, const int* in_sizes, int n_in,
                              void* d_out, int out_size) {
    const float4* xg = (const float4*)d_in[0];   // (B, 64, 4) f32
    const float4* wg = (const float4*)d_in[1];   // (64, 64, 4) f32
    const float4* tg = (const float4*)d_in[2];   // (64, 4) f32
    float* out = (float*)d_out;

    int B = in_sizes[0] / 256;                   // 131072
    int ntiles = B / MTILE;                      // 2048
    int grid = 148;
    if (grid > ntiles) grid = ntiles;

    cudaFuncSetAttribute(gemm_kernel,
                         cudaFuncAttributeMaxDynamicSharedMemorySize, SM_TOTAL);

    build_w<<<32, 256>>>(wg, tg);
    gemm_kernel<<<grid, NTHR, SM_TOTAL>>>(xg, out, ntiles);
}